// round 2
// baseline (speedup 1.0000x reference)
#include <cuda_runtime.h>
#include <cuda_bf16.h>

#define NPTS 10000
#define KNB 32
#define KSZ 6
#define MCELLS 216   // 6*6*6
#define MAXC 64

// ---------------- device scratch (static: no allocs allowed) ----------------
__device__ float4 g_pairs[NPTS * KNB];                       // packed geometry per (point, neighbor)
__device__ float  g_cnt[NPTS];                               // neighbor counts
__device__ float  g_A[(size_t)NPTS * MCELLS * MAXC];         // scatter output, max Cin=64 (553 MB)
__device__ float  g_acc[NPTS * MAXC];                        // GEMM split-K accumulator
__device__ float  g_X1[NPTS * 64];
__device__ float  g_X2[NPTS * 64];
__device__ float  g_X3[NPTS * 32];
__device__ int    g_mask_is_u8;                              // 0 = int32 layout, 1 = uint8 layout

__device__ __forceinline__ float sgnf(float v) { return (v > 0.f) ? 1.f : ((v < 0.f) ? -1.f : 0.f); }

// ---------------- mask dtype detection ----------------
// Scan only the first NPTS*KNB BYTES (safe under both layouts). For an int32
// mask (values 0/1), every byte at offset %4 != 0 is zero. For a uint8 mask,
// ~1/3 of all bytes are 1, so some off-aligned byte is nonzero. atomicOr is
// idempotent -> deterministic across graph replays.
__global__ void detect_mask_kernel(const unsigned char* __restrict__ bytes) {
    int i = blockIdx.x * 256 + threadIdx.x;
    if (i >= NPTS * KNB) return;
    if ((i & 3) != 0 && bytes[i] != 0) atomicOr(&g_mask_is_u8, 1);
}

__device__ __forceinline__ unsigned read_mask(const void* m, int idx) {
    if (g_mask_is_u8) return ((const unsigned char*)m)[idx] ? 1u : 0u;
    return ((const int*)m)[idx] ? 1u : 0u;
}

// ---------------- geometry: ball->cube map + trilinear corners (once for all layers) ----------------
__global__ void geom_kernel(const float* __restrict__ pos, const int* __restrict__ nidx,
                            const void* __restrict__ nmask) {
    int idx = blockIdx.x * blockDim.x + threadIdx.x;
    if (idx >= NPTS * KNB) return;
    int j = idx >> 5;               // KNB = 32
    int n = nidx[idx];
    unsigned m = read_mask(nmask, idx);

    const float EPS = 1e-12f;
    float x = (pos[n * 3 + 0] - pos[j * 3 + 0]) * (2.0f / 3.0f);
    float y = (pos[n * 3 + 1] - pos[j * 3 + 1]) * (2.0f / 3.0f);
    float z = (pos[n * 3 + 2] - pos[j * 3 + 2]) * (2.0f / 3.0f);

    float sq = x * x + y * y + z * z;
    float norm = sqrtf(fmaxf(sq, EPS));
    float rho2 = x * x + y * y;
    bool in_cone = (1.25f * z * z > rho2);
    float s, zc;
    if (in_cone) { s = sqrtf(3.0f * norm / (norm + fabsf(z))); zc = sgnf(z) * norm; }
    else         { s = norm / sqrtf(fmaxf(rho2, EPS));         zc = 1.5f * z; }
    float xc = x * s, yc = y * s;
    if (sq < EPS) { xc = 0.f; yc = 0.f; zc = 0.f; }

    float sq_xy = xc * xc + yc * yc;
    float norm_xy = sqrtf(fmaxf(sq_xy, EPS));
    bool x_major = fabsf(yc) <= fabsf(xc);
    float xd = (fabsf(xc) < EPS) ? 1.f : xc;
    float yd = (fabsf(yc) < EPS) ? 1.f : yc;
    float tx = sgnf(xc) * norm_xy, ty = sgnf(yc) * norm_xy;
    const float FOPI = 1.2732395447351628f;  // 4/pi
    float xq, yq;
    if (x_major) { xq = tx;                        yq = tx * FOPI * atanf(yc / xd); }
    else         { xq = ty * FOPI * atanf(xc / yd); yq = ty; }
    if (sq_xy < EPS) { xq = 0.f; yq = 0.f; }

    // align_corners coords in [0, 5]
    float c0 = (xq + 1.f) * 2.5f, c1 = (yq + 1.f) * 2.5f, c2 = (zc + 1.f) * 2.5f;
    float f0 = floorf(c0), f1 = floorf(c1), f2 = floorf(c2);
    int i0x = min(max((int)f0, 0), KSZ - 1);
    int i0y = min(max((int)f1, 0), KSZ - 1);
    int i0z = min(max((int)f2, 0), KSZ - 1);
    unsigned packed = (unsigned)i0x | ((unsigned)i0y << 8) | ((unsigned)i0z << 16) | (m << 24);
    g_pairs[idx] = make_float4(__uint_as_float(packed), c0 - f0, c1 - f1, c2 - f2);
}

__global__ void count_kernel(const void* __restrict__ nmask) {
    int j = blockIdx.x * blockDim.x + threadIdx.x;
    if (j >= NPTS) return;
    int s = 0;
#pragma unroll
    for (int k = 0; k < KNB; k++) s += (int)read_mask(nmask, j * KNB + k);
    g_cnt[j] = (float)s;
}

// ---------------- scatter: build A[point][cell*CIN + c] in shared, write to global ----------------
// src_sel: 0 -> use X pointer (feats), 1 -> g_X1, 2 -> g_X2
template <int CIN>
__global__ void scatter_kernel(const float* __restrict__ X, const int* __restrict__ nidx, int src_sel) {
    extern __shared__ float sm[];
    float* A   = sm;                               // MCELLS*CIN
    float* feat = A + MCELLS * CIN;                // KNB*CIN
    float* wS  = feat + KNB * CIN;                 // 256
    unsigned short* cellS = (unsigned short*)(wS + KNB * 8);  // 256

    const float* __restrict__ src = (src_sel == 1) ? g_X1 : ((src_sel == 2) ? g_X2 : X);

    int j = blockIdx.x;
    int tid = threadIdx.x;

    for (int i = tid; i < MCELLS * CIN; i += 256) A[i] = 0.f;
    for (int i = tid; i < KNB * CIN; i += 256) {
        int k = i / CIN, c = i - k * CIN;
        feat[i] = src[(size_t)nidx[j * KNB + k] * CIN + c];
    }
    if (tid < KNB) {
        float4 p = g_pairs[j * KNB + tid];
        unsigned pk = __float_as_uint(p.x);
        int ix0 = pk & 255, iy0 = (pk >> 8) & 255, iz0 = (pk >> 16) & 255;
        float mk = (pk >> 24) ? 1.f : 0.f;
        int ix[2] = { ix0, min(ix0 + 1, KSZ - 1) };
        int iy[2] = { iy0, min(iy0 + 1, KSZ - 1) };
        int iz[2] = { iz0, min(iz0 + 1, KSZ - 1) };
        float wx[2] = { 1.f - p.y, p.y };
        float wy[2] = { 1.f - p.z, p.z };
        float wz[2] = { 1.f - p.w, p.w };
#pragma unroll
        for (int c8 = 0; c8 < 8; c8++) {
            int cx = c8 >> 2, cy = (c8 >> 1) & 1, cz = c8 & 1;
            cellS[tid * 8 + c8] = (unsigned short)((ix[cx] * KSZ + iy[cy]) * KSZ + iz[cz]);
            wS[tid * 8 + c8] = wx[cx] * wy[cy] * wz[cz] * mk;
        }
    }
    __syncthreads();

    for (int base = 0; base < KNB * 8 * CIN; base += 256) {
        int idx = base + tid;
        int p = idx / CIN, c = idx - p * CIN;
        float w = wS[p];
        if (w != 0.f) atomicAdd(&A[cellS[p] * CIN + c], w * feat[(p >> 3) * CIN + c]);
    }
    __syncthreads();

    float4* dst = (float4*)(g_A + (size_t)j * MCELLS * CIN);
    const float4* s4 = (const float4*)A;
    for (int i = tid; i < MCELLS * CIN / 4; i += 256) dst[i] = s4[i];
}

__global__ void zero_acc_kernel() {
    int i = blockIdx.x * 256 + threadIdx.x;
    if (i < NPTS * MAXC) g_acc[i] = 0.f;
}

// ---------------- split-K fp32 GEMM: g_acc[N,BN] += A[N,Kd] @ W[Kd,BN] ----------------
#define BM 64
#define BK 32
#define ASTRIDE 68

template <int BN, int TN>
__global__ void gemm_kernel(const float* __restrict__ W, int Kd, int cps) {
    __shared__ float As[BK * ASTRIDE];
    __shared__ float Bs[BK * BN];
    int tid = threadIdx.x;                 // 128 threads
    int tx = tid & 15, ty = tid >> 4;
    int m0 = blockIdx.x * BM;
    int row0 = ty * 8, col0 = tx * TN;

    float acc[8][TN];
#pragma unroll
    for (int i = 0; i < 8; i++)
#pragma unroll
        for (int n = 0; n < TN; n++) acc[i][n] = 0.f;

    int chunk0 = blockIdx.y * cps;
    for (int ci = 0; ci < cps; ci++) {
        int kd0 = (chunk0 + ci) * BK;
        // A tile: 64 rows x 32 k, transposed into shared
#pragma unroll
        for (int i = 0; i < 4; i++) {
            int e = i * 128 + tid;
            int r = e >> 3, c4 = e & 7;
            float4 v = make_float4(0.f, 0.f, 0.f, 0.f);
            if (m0 + r < NPTS) v = *(const float4*)(g_A + (size_t)(m0 + r) * Kd + kd0 + c4 * 4);
            As[(c4 * 4 + 0) * ASTRIDE + r] = v.x;
            As[(c4 * 4 + 1) * ASTRIDE + r] = v.y;
            As[(c4 * 4 + 2) * ASTRIDE + r] = v.z;
            As[(c4 * 4 + 3) * ASTRIDE + r] = v.w;
        }
        // B tile: 32 k x BN
#pragma unroll
        for (int i = 0; i < BK * BN / 512; i++) {
            int e = i * 128 + tid;
            int kr = e / (BN / 4), c4 = e % (BN / 4);
            *(float4*)(Bs + kr * BN + c4 * 4) = *(const float4*)(W + (size_t)(kd0 + kr) * BN + c4 * 4);
        }
        __syncthreads();
#pragma unroll 8
        for (int k = 0; k < BK; k++) {
            float a[8];
            *(float4*)(a)     = *(const float4*)(As + k * ASTRIDE + row0);
            *(float4*)(a + 4) = *(const float4*)(As + k * ASTRIDE + row0 + 4);
            float b[TN];
            if (TN == 4) { *(float4*)b = *(const float4*)(Bs + k * BN + col0); }
            else         { b[0] = Bs[k * BN + col0]; b[1] = Bs[k * BN + col0 + 1]; }
#pragma unroll
            for (int i = 0; i < 8; i++)
#pragma unroll
                for (int n = 0; n < TN; n++) acc[i][n] += a[i] * b[n];
        }
        __syncthreads();
    }
#pragma unroll
    for (int i = 0; i < 8; i++) {
        int r = m0 + row0 + i;
        if (r < NPTS)
#pragma unroll
            for (int n = 0; n < TN; n++) atomicAdd(&g_acc[r * BN + col0 + n], acc[i][n]);
    }
}

// ---------------- finalize: normalize by neighbor count, + bias, ReLU ----------------
// dst_sel: 1 -> g_X1, 2 -> g_X2, 3 -> g_X3
__global__ void finalize_kernel(const float* __restrict__ bias, int Cout, int dst_sel) {
    int idx = blockIdx.x * 256 + threadIdx.x;
    if (idx >= NPTS * Cout) return;
    int j = idx / Cout, co = idx - j * Cout;
    float v = g_acc[idx];
    float c = g_cnt[j];
    if (c > 0.f) v /= c;
    v = fmaxf(v + bias[co], 0.f);
    if (dst_sel == 1) g_X1[idx] = v;
    else if (dst_sel == 2) g_X2[idx] = v;
    else g_X3[idx] = v;
}

// ---------------- fused FC chain: 32->64->64->32->3 ----------------
__global__ void fc_kernel(const float* __restrict__ Wf1, const float* __restrict__ bf1,
                          const float* __restrict__ Wf2, const float* __restrict__ bf2,
                          const float* __restrict__ Wf3, const float* __restrict__ bf3,
                          const float* __restrict__ Wo,  const float* __restrict__ bo,
                          float* __restrict__ out) {
    __shared__ float w1[32 * 64], w2[64 * 64], w3[64 * 32], wo[32 * 3];
    __shared__ float bb1[64], bb2[64], bb3[32], bbo[3];
    int tid = threadIdx.x;  // 128
    for (int i = tid; i < 2048; i += 128) w1[i] = Wf1[i];
    for (int i = tid; i < 4096; i += 128) w2[i] = Wf2[i];
    for (int i = tid; i < 2048; i += 128) w3[i] = Wf3[i];
    for (int i = tid; i < 96; i += 128) wo[i] = Wo[i];
    if (tid < 64) { bb1[tid] = bf1[tid]; bb2[tid] = bf2[tid]; }
    if (tid < 32) bb3[tid] = bf3[tid];
    if (tid < 3)  bbo[tid] = bo[tid];
    __syncthreads();

    int j = blockIdx.x * 128 + tid;
    if (j >= NPTS) return;

    float x[32];
#pragma unroll
    for (int i = 0; i < 32; i++) x[i] = g_X3[j * 32 + i];
    float y[64];
    for (int o = 0; o < 64; o++) {
        float s = bb1[o];
#pragma unroll
        for (int i = 0; i < 32; i++) s += x[i] * w1[i * 64 + o];
        y[o] = fmaxf(s, 0.f);
    }
    float z[64];
    for (int o = 0; o < 64; o++) {
        float s = bb2[o];
#pragma unroll
        for (int i = 0; i < 64; i++) s += y[i] * w2[i * 64 + o];
        z[o] = fmaxf(s, 0.f);
    }
    float t[32];
    for (int o = 0; o < 32; o++) {
        float s = bb3[o];
#pragma unroll
        for (int i = 0; i < 64; i++) s += z[i] * w3[i * 32 + o];
        t[o] = fmaxf(s, 0.f);
    }
    for (int o = 0; o < 3; o++) {
        float s = bbo[o];
#pragma unroll
        for (int i = 0; i < 32; i++) s += t[i] * wo[i * 3 + o];
        out[j * 3 + o] = s;
    }
}

// ---------------- launch ----------------
extern "C" void kernel_launch(void* const* d_in, const int* in_sizes, int n_in,
                              void* d_out, int out_size) {
    const float* feats = (const float*)d_in[0];
    const float* pos   = (const float*)d_in[1];
    const int*   nidx  = (const int*)d_in[2];
    const void*  nmask = d_in[3];
    const float* W1 = (const float*)d_in[4];  const float* b1 = (const float*)d_in[5];
    const float* W2 = (const float*)d_in[6];  const float* b2 = (const float*)d_in[7];
    const float* W3 = (const float*)d_in[8];  const float* b3 = (const float*)d_in[9];
    const float* Wf1 = (const float*)d_in[10]; const float* bf1 = (const float*)d_in[11];
    const float* Wf2 = (const float*)d_in[12]; const float* bf2 = (const float*)d_in[13];
    const float* Wf3 = (const float*)d_in[14]; const float* bf3 = (const float*)d_in[15];
    const float* Wo  = (const float*)d_in[16]; const float* bo  = (const float*)d_in[17];
    float* out = (float*)d_out;

    const int SMEM64 = (MCELLS * 64 + KNB * 64 + 256) * 4 + 512;  // 65024 B
    const int SMEM4  = (MCELLS * 4  + KNB * 4  + 256) * 4 + 512;  // 5504 B
    cudaFuncSetAttribute(scatter_kernel<64>, cudaFuncAttributeMaxDynamicSharedMemorySize, SMEM64);
    cudaFuncSetAttribute(scatter_kernel<4>,  cudaFuncAttributeMaxDynamicSharedMemorySize, SMEM4);

    detect_mask_kernel<<<(NPTS * KNB + 255) / 256, 256>>>((const unsigned char*)nmask);
    geom_kernel<<<(NPTS * KNB + 255) / 256, 256>>>(pos, nidx, nmask);
    count_kernel<<<(NPTS + 255) / 256, 256>>>(nmask);

    const int MBLK = (NPTS + BM - 1) / BM;  // 157

    // layer 1: Cin=4 -> Cout=64, Kd=864 (27 chunks, splitK=3 x 9)
    scatter_kernel<4><<<NPTS, 256, SMEM4>>>(feats, nidx, 0);
    zero_acc_kernel<<<(NPTS * MAXC + 255) / 256, 256>>>();
    gemm_kernel<64, 4><<<dim3(MBLK, 3), 128>>>(W1, MCELLS * 4, 9);
    finalize_kernel<<<(NPTS * 64 + 255) / 256, 256>>>(b1, 64, 1);

    // layer 2: 64 -> 64, Kd=13824 (432 chunks, splitK=8 x 54)
    scatter_kernel<64><<<NPTS, 256, SMEM64>>>(nullptr, nidx, 1);
    zero_acc_kernel<<<(NPTS * MAXC + 255) / 256, 256>>>();
    gemm_kernel<64, 4><<<dim3(MBLK, 8), 128>>>(W2, MCELLS * 64, 54);
    finalize_kernel<<<(NPTS * 64 + 255) / 256, 256>>>(b2, 64, 2);

    // layer 3: 64 -> 32
    scatter_kernel<64><<<NPTS, 256, SMEM64>>>(nullptr, nidx, 2);
    zero_acc_kernel<<<(NPTS * MAXC + 255) / 256, 256>>>();
    gemm_kernel<32, 2><<<dim3(MBLK, 8), 128>>>(W3, MCELLS * 64, 54);
    finalize_kernel<<<(NPTS * 32 + 255) / 256, 256>>>(b3, 32, 3);

    // FC head
    fc_kernel<<<(NPTS + 127) / 128, 128>>>(Wf1, bf1, Wf2, bf2, Wf3, bf3, Wo, bo, out);
}